// round 1
// baseline (speedup 1.0000x reference)
#include <cuda_runtime.h>
#include <math.h>

// Problem constants
#define BB 4
#define SS 2048
#define MM 1024
#define FF 4096
static const long SMTOT = (long)SS * MM;          // 2,097,152 elems per batch
static const long SM4   = SMTOT / 4;

// ---------------------------------------------------------------------------
// Scratch (device globals: allocation inside kernel_launch is forbidden)
// ---------------------------------------------------------------------------
__device__ float g_scores[(long)BB * SS * SS];    // 64 MB  (attn probs in-place)
__device__ float g_ctx   [(long)BB * SS * MM];    // 32 MB
__device__ float g_pre1  [(long)BB * SS * MM];    // o + x
__device__ float g_h     [(long)BB * SS * MM];    // LN1 output
__device__ float g_ff1   [(long)BB * SS * FF];    // 128 MB
__device__ float g_pre2  [(long)BB * SS * MM];    // ff2 + h
__device__ float g_part  [BB * 256 * 2];          // LN partial (sum, sumsq)
__device__ float g_stats [BB * 2];                // LN (mean, rstd)

// ---------------------------------------------------------------------------
// Tiled SGEMM: C[m,n] = epilogue( sum_k A[m,k] * B(k,n) )
//   BT=true : B is [N,K] row-major (contract over columns of both) — "NT"
//   BT=false: B is [K,N] row-major — "NN"
// Assumes: lda == Kdim, ldb == (BT ? Kdim : Ndim), ldc == Ndim,
//          M,N multiple of 128, K multiple of 8. All true for every call here.
// EPI: 0 = *alpha
//      1 = plain
//      2 = + R           (residual)
//      3 = relu(+bias)
//      4 = + bias + R
// ---------------------------------------------------------------------------
template<bool BT, int EPI>
__global__ __launch_bounds__(256, 2)
void gemm_k(const float* __restrict__ A, const float* __restrict__ Bm,
            float* __restrict__ C,
            const float* __restrict__ bias, const float* __restrict__ R,
            int Kdim, int Ndim,
            long sA, long sB, long sC,
            float alpha)
{
    __shared__ float As[8][128];
    __shared__ float Bs[8][128];

    const int bz = blockIdx.z;
    A  += (long)bz * sA;
    Bm += (long)bz * sB;
    C  += (long)bz * sC;

    const int m0  = blockIdx.y * 128;
    const int n0  = blockIdx.x * 128;
    const int tid = threadIdx.x;
    const int tx  = tid & 15;        // 0..15  -> n micro-tile
    const int ty  = tid >> 4;        // 0..15  -> m micro-tile

    // loader indices (transposed loads along K)
    const int lrow = tid >> 1;       // 0..127
    const int lk   = (tid & 1) * 4;  // 0 or 4

    const float* Ap = A + (long)(m0 + lrow) * Kdim + lk;
    const float* Bp;
    int bnr = 0, bnc = 0;
    if (BT) {
        Bp = Bm + (long)(n0 + lrow) * Kdim + lk;
    } else {
        bnr = tid >> 5;              // 0..7   (k row)
        bnc = (tid & 31) * 4;        // 0..124 (n col)
        Bp = Bm + (long)bnr * Ndim + n0 + bnc;
    }

    float acc[8][8];
    #pragma unroll
    for (int i = 0; i < 8; i++)
        #pragma unroll
        for (int j = 0; j < 8; j++) acc[i][j] = 0.f;

    for (int k0 = 0; k0 < Kdim; k0 += 8) {
        float4 av = *(const float4*)(Ap + k0);
        As[lk + 0][lrow] = av.x;
        As[lk + 1][lrow] = av.y;
        As[lk + 2][lrow] = av.z;
        As[lk + 3][lrow] = av.w;
        if (BT) {
            float4 bv = *(const float4*)(Bp + k0);
            Bs[lk + 0][lrow] = bv.x;
            Bs[lk + 1][lrow] = bv.y;
            Bs[lk + 2][lrow] = bv.z;
            Bs[lk + 3][lrow] = bv.w;
        } else {
            float4 bv = *(const float4*)(Bp + (long)k0 * Ndim);
            *(float4*)&Bs[bnr][bnc] = bv;
        }
        __syncthreads();

        #pragma unroll
        for (int kk = 0; kk < 8; kk++) {
            float4 a0 = *(const float4*)&As[kk][ty * 8];
            float4 a1 = *(const float4*)&As[kk][ty * 8 + 4];
            float4 b0 = *(const float4*)&Bs[kk][tx * 8];
            float4 b1 = *(const float4*)&Bs[kk][tx * 8 + 4];
            float a[8] = {a0.x, a0.y, a0.z, a0.w, a1.x, a1.y, a1.z, a1.w};
            float b[8] = {b0.x, b0.y, b0.z, b0.w, b1.x, b1.y, b1.z, b1.w};
            #pragma unroll
            for (int i = 0; i < 8; i++)
                #pragma unroll
                for (int j = 0; j < 8; j++)
                    acc[i][j] = fmaf(a[i], b[j], acc[i][j]);
        }
        __syncthreads();
    }

    // ------------------- epilogue -------------------
    float bs[8] = {0, 0, 0, 0, 0, 0, 0, 0};
    if (EPI == 3 || EPI == 4) {
        float4 q0 = *(const float4*)&bias[n0 + tx * 8];
        float4 q1 = *(const float4*)&bias[n0 + tx * 8 + 4];
        bs[0] = q0.x; bs[1] = q0.y; bs[2] = q0.z; bs[3] = q0.w;
        bs[4] = q1.x; bs[5] = q1.y; bs[6] = q1.z; bs[7] = q1.w;
    }
    #pragma unroll
    for (int i = 0; i < 8; i++) {
        long m   = m0 + ty * 8 + i;
        long off = m * (long)Ndim + n0 + tx * 8;
        float v[8];
        #pragma unroll
        for (int j = 0; j < 8; j++) v[j] = acc[i][j];

        if (EPI == 0) {
            #pragma unroll
            for (int j = 0; j < 8; j++) v[j] *= alpha;
        }
        if (EPI == 3 || EPI == 4) {
            #pragma unroll
            for (int j = 0; j < 8; j++) v[j] += bs[j];
        }
        if (EPI == 3) {
            #pragma unroll
            for (int j = 0; j < 8; j++) v[j] = fmaxf(v[j], 0.f);
        }
        if (EPI == 2 || EPI == 4) {
            float4 r0 = *(const float4*)&R[off];
            float4 r1 = *(const float4*)&R[off + 4];
            v[0] += r0.x; v[1] += r0.y; v[2] += r0.z; v[3] += r0.w;
            v[4] += r1.x; v[5] += r1.y; v[6] += r1.z; v[7] += r1.w;
        }
        *(float4*)&C[off]     = make_float4(v[0], v[1], v[2], v[3]);
        *(float4*)&C[off + 4] = make_float4(v[4], v[5], v[6], v[7]);
    }
}

// ---------------------------------------------------------------------------
// Row softmax over 2048 columns; one block per row; row kept in registers.
// ---------------------------------------------------------------------------
__global__ __launch_bounds__(256)
void softmax_k(float* __restrict__ data)
{
    long row = blockIdx.x;
    float* p = data + row * (long)SS;
    int t = threadIdx.x;

    float v[8];
    float mx = -INFINITY;
    #pragma unroll
    for (int i = 0; i < 8; i++) {
        v[i] = p[t + i * 256];
        mx = fmaxf(mx, v[i]);
    }
    __shared__ float red[256];
    red[t] = mx; __syncthreads();
    for (int s = 128; s > 0; s >>= 1) {
        if (t < s) red[t] = fmaxf(red[t], red[t + s]);
        __syncthreads();
    }
    mx = red[0];
    __syncthreads();

    float sum = 0.f;
    #pragma unroll
    for (int i = 0; i < 8; i++) {
        v[i] = __expf(v[i] - mx);
        sum += v[i];
    }
    red[t] = sum; __syncthreads();
    for (int s = 128; s > 0; s >>= 1) {
        if (t < s) red[t] += red[t + s];
        __syncthreads();
    }
    float inv = 1.f / red[0];
    #pragma unroll
    for (int i = 0; i < 8; i++) p[t + i * 256] = v[i] * inv;
}

// ---------------------------------------------------------------------------
// LayerNorm over the full (S, M) plane per batch. Deterministic 3-stage:
// per-block partials -> finalize(mean, rstd) -> apply.
// ---------------------------------------------------------------------------
__global__ __launch_bounds__(256)
void ln_reduce_k(const float* __restrict__ xx, float* __restrict__ part)
{
    int b = blockIdx.y;
    const float4* p = (const float4*)(xx + (long)b * SMTOT) + (long)blockIdx.x * 2048;
    float s = 0.f, q = 0.f;
    for (int i = threadIdx.x; i < 2048; i += 256) {
        float4 v = p[i];
        s += v.x + v.y + v.z + v.w;
        q += v.x * v.x + v.y * v.y + v.z * v.z + v.w * v.w;
    }
    __shared__ float rs[256], rq[256];
    rs[threadIdx.x] = s; rq[threadIdx.x] = q; __syncthreads();
    for (int st = 128; st > 0; st >>= 1) {
        if (threadIdx.x < st) {
            rs[threadIdx.x] += rs[threadIdx.x + st];
            rq[threadIdx.x] += rq[threadIdx.x + st];
        }
        __syncthreads();
    }
    if (threadIdx.x == 0) {
        int idx = (b * 256 + blockIdx.x) * 2;
        part[idx]     = rs[0];
        part[idx + 1] = rq[0];
    }
}

__global__ __launch_bounds__(256)
void ln_finalize_k(const float* __restrict__ part, float* __restrict__ stats)
{
    int b = blockIdx.x;
    int t = threadIdx.x;
    float s = part[(b * 256 + t) * 2];
    float q = part[(b * 256 + t) * 2 + 1];
    __shared__ float rs[256], rq[256];
    rs[t] = s; rq[t] = q; __syncthreads();
    for (int st = 128; st > 0; st >>= 1) {
        if (t < st) { rs[t] += rs[t + st]; rq[t] += rq[t + st]; }
        __syncthreads();
    }
    if (t == 0) {
        float mean = rs[0] / (float)SMTOT;
        float var  = rq[0] / (float)SMTOT - mean * mean;
        stats[b * 2]     = mean;
        stats[b * 2 + 1] = rsqrtf(var + 1e-5f);
    }
}

__global__ __launch_bounds__(256)
void ln_apply_k(const float* __restrict__ xx, const float* __restrict__ w,
                const float* __restrict__ bb, const float* __restrict__ stats,
                float* __restrict__ y)
{
    long i = (long)blockIdx.x * 256 + threadIdx.x;   // float4 index
    int b  = (int)(i / SM4);
    long sm = i - (long)b * SM4;
    float mean = stats[b * 2];
    float rstd = stats[b * 2 + 1];
    float4 v  = ((const float4*)xx)[i];
    float4 wv = ((const float4*)w)[sm];
    float4 bv = ((const float4*)bb)[sm];
    float4 o;
    o.x = (v.x - mean) * rstd * wv.x + bv.x;
    o.y = (v.y - mean) * rstd * wv.y + bv.y;
    o.z = (v.z - mean) * rstd * wv.z + bv.z;
    o.w = (v.w - mean) * rstd * wv.w + bv.w;
    ((float4*)y)[i] = o;
}

// ---------------------------------------------------------------------------
// Launch
// ---------------------------------------------------------------------------
extern "C" void kernel_launch(void* const* d_in, const int* in_sizes, int n_in,
                              void* d_out, int out_size)
{
    const float* x     = (const float*)d_in[0];
    const float* w_out = (const float*)d_in[1];
    const float* ln1_w = (const float*)d_in[2];
    const float* ln1_b = (const float*)d_in[3];
    const float* w1    = (const float*)d_in[4];
    const float* b1    = (const float*)d_in[5];
    const float* w2    = (const float*)d_in[6];
    const float* b2    = (const float*)d_in[7];
    const float* ln2_w = (const float*)d_in[8];
    const float* ln2_b = (const float*)d_in[9];
    float* out = (float*)d_out;

    float *scores, *ctx, *pre1, *h, *ff1, *pre2, *part, *stats;
    cudaGetSymbolAddress((void**)&scores, g_scores);
    cudaGetSymbolAddress((void**)&ctx,    g_ctx);
    cudaGetSymbolAddress((void**)&pre1,   g_pre1);
    cudaGetSymbolAddress((void**)&h,      g_h);
    cudaGetSymbolAddress((void**)&ff1,    g_ff1);
    cudaGetSymbolAddress((void**)&pre2,   g_pre2);
    cudaGetSymbolAddress((void**)&part,   g_part);
    cudaGetSymbolAddress((void**)&stats,  g_stats);

    dim3 blk(256);
    const float scale = 1.0f / 32.0f;   // 1/sqrt(1024)
    const long BS = (long)BB * SS;      // 8192 folded rows

    // 1. scores = (x @ x^T) * scale           [per-batch NT, M=N=2048, K=1024]
    gemm_k<true, 0><<<dim3(SS / 128, SS / 128, BB), blk>>>(
        x, x, scores, nullptr, nullptr, MM, SS, SMTOT, SMTOT, (long)SS * SS, scale);

    // 2. softmax rows (in place)
    softmax_k<<<(unsigned)(BB * SS), blk>>>(scores);

    // 3. ctx = attn @ x                       [per-batch NN, M=2048, N=1024, K=2048]
    gemm_k<false, 1><<<dim3(MM / 128, SS / 128, BB), blk>>>(
        scores, x, ctx, nullptr, nullptr, SS, MM, (long)SS * SS, SMTOT, SMTOT, 1.f);

    // 4. pre1 = ctx @ w_out^T + x             [folded NT, M=8192, N=1024, K=1024]
    gemm_k<true, 2><<<dim3(MM / 128, (unsigned)(BS / 128), 1), blk>>>(
        ctx, w_out, pre1, nullptr, x, MM, MM, 0, 0, 0, 1.f);

    // 5. h = LN1(pre1)
    ln_reduce_k<<<dim3(256, BB), blk>>>(pre1, part);
    ln_finalize_k<<<BB, blk>>>(part, stats);
    ln_apply_k<<<(unsigned)((BB * SMTOT / 4) / 256), blk>>>(pre1, ln1_w, ln1_b, stats, h);

    // 6. ff1 = relu(h @ w1^T + b1)            [folded NT, M=8192, N=4096, K=1024]
    gemm_k<true, 3><<<dim3(FF / 128, (unsigned)(BS / 128), 1), blk>>>(
        h, w1, ff1, b1, nullptr, MM, FF, 0, 0, 0, 1.f);

    // 7. pre2 = ff1 @ w2^T + b2 + h           [folded NT, M=8192, N=1024, K=4096]
    gemm_k<true, 4><<<dim3(MM / 128, (unsigned)(BS / 128), 1), blk>>>(
        ff1, w2, pre2, b2, h, FF, MM, 0, 0, 0, 1.f);

    // 8. out = LN2(pre2)
    ln_reduce_k<<<dim3(256, BB), blk>>>(pre2, part);
    ln_finalize_k<<<BB, blk>>>(part, stats);
    ln_apply_k<<<(unsigned)((BB * SMTOT / 4) / 256), blk>>>(pre2, ln2_w, ln2_b, stats, out);
}

// round 3
// speedup vs baseline: 1.8111x; 1.8111x over previous
#include <cuda_runtime.h>
#include <stdint.h>
#include <math.h>

// ---------------------------------------------------------------------------
// Problem constants
// ---------------------------------------------------------------------------
#define BB 4
#define SS 2048
#define MM 1024
#define FF 4096
static const long SMTOT = (long)SS * MM;
static const long SM4   = SMTOT / 4;

// ---------------------------------------------------------------------------
// Scratch (device globals)
// ---------------------------------------------------------------------------
__device__ float g_scores[(long)BB * SS * SS];   // 64 MB
__device__ float g_ctx   [(long)BB * SS * MM];
__device__ float g_xt    [(long)BB * SS * MM];
__device__ float g_pre1  [(long)BB * SS * MM];
__device__ float g_h     [(long)BB * SS * MM];
__device__ float g_ff1   [(long)BB * SS * FF];   // 128 MB
__device__ float g_pre2  [(long)BB * SS * MM];
__device__ float g_part  [BB * 256 * 2];
__device__ float g_stats [BB * 2];

// ---------------------------------------------------------------------------
// tf32 helpers (sm_80+ PTX — works on plain sm_100 target)
// ---------------------------------------------------------------------------
static __device__ __forceinline__ uint32_t f2tf32(float f) {
    uint32_t r;
    asm("cvt.rn.tf32.f32 %0, %1;" : "=r"(r) : "f"(f));
    return r;
}

static __device__ __forceinline__ void mma_tf32_16n8k8(
    float& c0, float& c1, float& c2, float& c3,
    uint32_t a0, uint32_t a1, uint32_t a2, uint32_t a3,
    uint32_t b0, uint32_t b1)
{
    asm volatile(
        "mma.sync.aligned.m16n8k8.row.col.f32.tf32.tf32.f32 "
        "{%0,%1,%2,%3}, {%4,%5,%6,%7}, {%8,%9}, {%0,%1,%2,%3};"
        : "+f"(c0), "+f"(c1), "+f"(c2), "+f"(c3)
        : "r"(a0), "r"(a1), "r"(a2), "r"(a3), "r"(b0), "r"(b1));
}

// ---------------------------------------------------------------------------
// tf32 NT GEMM via mma.sync:  C[m,n] = epi( sum_k A[m,k] * B[n,k] )
// A: [M,K] row-major, B: [N,K] row-major. M%128==0, N%128==0, K%32==0.
// BM=BN=128, BK=32; 256 threads; warps 2(m) x 4(n); warp tile 64x32.
// Smem rows padded to 36 floats -> fragment LDS bank = 4*row+col (conflict-free).
// EPI: 0=*alpha  1=plain  2=+R  3=relu(+bias)  4=+bias+R
// ---------------------------------------------------------------------------
#define PAD 36
#define TILE_U32 (128 * PAD)          // per-buffer per-matrix, in uint32
#define SMEM_TOT (4 * TILE_U32 * 4)   // bytes: A0,A1,B0,B1

template<int EPI>
__global__ __launch_bounds__(256)
void gemm_mma(const float* __restrict__ A, const float* __restrict__ Bm,
              float* __restrict__ C, const float* __restrict__ bias,
              const float* __restrict__ R,
              int Kdim, int Ndim, long sA, long sB, long sC, float alpha)
{
    extern __shared__ __align__(16) uint32_t sm[];
    uint32_t* As[2] = { sm,                sm + TILE_U32 };
    uint32_t* Bs[2] = { sm + 2 * TILE_U32, sm + 3 * TILE_U32 };

    const int tid  = threadIdx.x;
    const int wid  = tid >> 5;
    const int lane = tid & 31;
    const int gid  = lane >> 2;      // 0..7
    const int lq   = lane & 3;       // 0..3
    const int wm   = wid >> 2;       // 0..1  (m)
    const int wn   = wid & 3;        // 0..3  (n)

    const long bz = blockIdx.z;
    const int  m0 = blockIdx.y * 128;
    const int  n0 = blockIdx.x * 128;

    // staging: thread loads 16 A floats + 16 B floats per BK tile
    const int lrow  = tid >> 1;        // 0..127
    const int khalf = (tid & 1) * 16;  // 0 or 16 (floats)

    const float* Ag = A  + bz * sA + (long)(m0 + lrow) * Kdim + khalf;
    const float* Bg = Bm + bz * sB + (long)(n0 + lrow) * Kdim + khalf;

    float acc[4][4][4];
    #pragma unroll
    for (int i = 0; i < 4; i++)
        #pragma unroll
        for (int j = 0; j < 4; j++)
            #pragma unroll
            for (int q = 0; q < 4; q++) acc[i][j][q] = 0.f;

    const int KT = Kdim >> 5;

    float4 ra[4], rb[4];
    #pragma unroll
    for (int j = 0; j < 4; j++) {
        ra[j] = *(const float4*)(Ag + j * 4);
        rb[j] = *(const float4*)(Bg + j * 4);
    }

    for (int kt = 0; kt < KT; kt++) {
        const int s = kt & 1;
        // stage (cvt.rn to tf32 once per element)
        {
            uint32_t* ap = As[s] + lrow * PAD + khalf;
            uint32_t* bp = Bs[s] + lrow * PAD + khalf;
            #pragma unroll
            for (int j = 0; j < 4; j++) {
                uint4 u;
                u.x = f2tf32(ra[j].x); u.y = f2tf32(ra[j].y);
                u.z = f2tf32(ra[j].z); u.w = f2tf32(ra[j].w);
                *(uint4*)(ap + j * 4) = u;
                uint4 v;
                v.x = f2tf32(rb[j].x); v.y = f2tf32(rb[j].y);
                v.z = f2tf32(rb[j].z); v.w = f2tf32(rb[j].w);
                *(uint4*)(bp + j * 4) = v;
            }
        }
        __syncthreads();

        if (kt + 1 < KT) {
            const float* an = Ag + (kt + 1) * 32;
            const float* bn = Bg + (kt + 1) * 32;
            #pragma unroll
            for (int j = 0; j < 4; j++) {
                ra[j] = *(const float4*)(an + j * 4);
                rb[j] = *(const float4*)(bn + j * 4);
            }
        }

        // compute 4 k8-steps from buffer s
        const uint32_t* ab = As[s];
        const uint32_t* bb = Bs[s];
        #pragma unroll
        for (int ks = 0; ks < 4; ks++) {
            const int kb = ks * 8;
            uint32_t af[4][4];
            #pragma unroll
            for (int mt = 0; mt < 4; mt++) {
                const int rA = wm * 64 + mt * 16 + gid;
                af[mt][0] = ab[(rA    ) * PAD + kb     + lq];
                af[mt][1] = ab[(rA + 8) * PAD + kb     + lq];
                af[mt][2] = ab[(rA    ) * PAD + kb + 4 + lq];
                af[mt][3] = ab[(rA + 8) * PAD + kb + 4 + lq];
            }
            uint32_t bf[4][2];
            #pragma unroll
            for (int nt = 0; nt < 4; nt++) {
                const int rB = wn * 32 + nt * 8 + gid;
                bf[nt][0] = bb[rB * PAD + kb     + lq];
                bf[nt][1] = bb[rB * PAD + kb + 4 + lq];
            }
            #pragma unroll
            for (int mt = 0; mt < 4; mt++)
                #pragma unroll
                for (int nt = 0; nt < 4; nt++)
                    mma_tf32_16n8k8(acc[mt][nt][0], acc[mt][nt][1],
                                    acc[mt][nt][2], acc[mt][nt][3],
                                    af[mt][0], af[mt][1], af[mt][2], af[mt][3],
                                    bf[nt][0], bf[nt][1]);
        }
        __syncthreads();
    }

    // ---------------- epilogue ----------------
    float* Cb = C + bz * sC;
    #pragma unroll
    for (int mt = 0; mt < 4; mt++) {
        const long row0 = m0 + wm * 64 + mt * 16 + gid;
        #pragma unroll
        for (int nt = 0; nt < 4; nt++) {
            const long col = n0 + wn * 32 + nt * 8 + lq * 2;
            float v0 = acc[mt][nt][0], v1 = acc[mt][nt][1];
            float v2 = acc[mt][nt][2], v3 = acc[mt][nt][3];
            if (EPI == 0) { v0 *= alpha; v1 *= alpha; v2 *= alpha; v3 *= alpha; }
            if (EPI == 3 || EPI == 4) {
                float2 b2 = *(const float2*)(bias + col);
                v0 += b2.x; v1 += b2.y; v2 += b2.x; v3 += b2.y;
            }
            if (EPI == 3) {
                v0 = fmaxf(v0, 0.f); v1 = fmaxf(v1, 0.f);
                v2 = fmaxf(v2, 0.f); v3 = fmaxf(v3, 0.f);
            }
            const long o0 = row0 * (long)Ndim + col;
            const long o1 = (row0 + 8) * (long)Ndim + col;
            if (EPI == 2 || EPI == 4) {
                float2 r0 = *(const float2*)(R + o0);
                float2 r1 = *(const float2*)(R + o1);
                v0 += r0.x; v1 += r0.y; v2 += r1.x; v3 += r1.y;
            }
            *(float2*)(Cb + o0) = make_float2(v0, v1);
            *(float2*)(Cb + o1) = make_float2(v2, v3);
        }
    }
}

// ---------------------------------------------------------------------------
// Transpose per batch: xt[b][m][s] = x[b][s][m]
// ---------------------------------------------------------------------------
__global__ __launch_bounds__(256)
void transpose_k(const float* __restrict__ x, float* __restrict__ xt)
{
    __shared__ float t[32][33];
    const int b  = blockIdx.z;
    const int bx = blockIdx.x * 32;   // m
    const int by = blockIdx.y * 32;   // s
    const float* xp = x  + (long)b * SMTOT;
    float*       yp = xt + (long)b * SMTOT;
    const int txx = threadIdx.x, tyy = threadIdx.y;
    #pragma unroll
    for (int i = 0; i < 4; i++)
        t[tyy + i * 8][txx] = xp[(long)(by + tyy + i * 8) * MM + bx + txx];
    __syncthreads();
    #pragma unroll
    for (int i = 0; i < 4; i++)
        yp[(long)(bx + tyy + i * 8) * SS + by + txx] = t[txx][tyy + i * 8];
}

// ---------------------------------------------------------------------------
// Row softmax over 2048 columns (in place)
// ---------------------------------------------------------------------------
__global__ __launch_bounds__(256)
void softmax_k(float* __restrict__ data)
{
    long row = blockIdx.x;
    float* p = data + row * (long)SS;
    int t = threadIdx.x;
    float v[8];
    float mx = -INFINITY;
    #pragma unroll
    for (int i = 0; i < 8; i++) { v[i] = p[t + i * 256]; mx = fmaxf(mx, v[i]); }
    __shared__ float red[256];
    red[t] = mx; __syncthreads();
    for (int s = 128; s > 0; s >>= 1) {
        if (t < s) red[t] = fmaxf(red[t], red[t + s]);
        __syncthreads();
    }
    mx = red[0];
    __syncthreads();
    float sum = 0.f;
    #pragma unroll
    for (int i = 0; i < 8; i++) { v[i] = __expf(v[i] - mx); sum += v[i]; }
    red[t] = sum; __syncthreads();
    for (int s = 128; s > 0; s >>= 1) {
        if (t < s) red[t] += red[t + s];
        __syncthreads();
    }
    float inv = 1.f / red[0];
    #pragma unroll
    for (int i = 0; i < 8; i++) p[t + i * 256] = v[i] * inv;
}

// ---------------------------------------------------------------------------
// LayerNorm over full (S,M) plane per batch — deterministic 3-stage
// ---------------------------------------------------------------------------
__global__ __launch_bounds__(256)
void ln_reduce_k(const float* __restrict__ xx, float* __restrict__ part)
{
    int b = blockIdx.y;
    const float4* p = (const float4*)(xx + (long)b * SMTOT) + (long)blockIdx.x * 2048;
    float s = 0.f, q = 0.f;
    for (int i = threadIdx.x; i < 2048; i += 256) {
        float4 v = p[i];
        s += v.x + v.y + v.z + v.w;
        q += v.x * v.x + v.y * v.y + v.z * v.z + v.w * v.w;
    }
    __shared__ float rs[256], rq[256];
    rs[threadIdx.x] = s; rq[threadIdx.x] = q; __syncthreads();
    for (int st = 128; st > 0; st >>= 1) {
        if (threadIdx.x < st) {
            rs[threadIdx.x] += rs[threadIdx.x + st];
            rq[threadIdx.x] += rq[threadIdx.x + st];
        }
        __syncthreads();
    }
    if (threadIdx.x == 0) {
        int idx = (b * 256 + blockIdx.x) * 2;
        part[idx]     = rs[0];
        part[idx + 1] = rq[0];
    }
}

__global__ __launch_bounds__(256)
void ln_finalize_k(const float* __restrict__ part, float* __restrict__ stats)
{
    int b = blockIdx.x, t = threadIdx.x;
    float s = part[(b * 256 + t) * 2];
    float q = part[(b * 256 + t) * 2 + 1];
    __shared__ float rs[256], rq[256];
    rs[t] = s; rq[t] = q; __syncthreads();
    for (int st = 128; st > 0; st >>= 1) {
        if (t < st) { rs[t] += rs[t + st]; rq[t] += rq[t + st]; }
        __syncthreads();
    }
    if (t == 0) {
        float mean = rs[0] / (float)SMTOT;
        float var  = rq[0] / (float)SMTOT - mean * mean;
        stats[b * 2]     = mean;
        stats[b * 2 + 1] = rsqrtf(var + 1e-5f);
    }
}

__global__ __launch_bounds__(256)
void ln_apply_k(const float* __restrict__ xx, const float* __restrict__ w,
                const float* __restrict__ bbp, const float* __restrict__ stats,
                float* __restrict__ y)
{
    long i = (long)blockIdx.x * 256 + threadIdx.x;
    int b  = (int)(i / SM4);
    long sm = i - (long)b * SM4;
    float mean = stats[b * 2];
    float rstd = stats[b * 2 + 1];
    float4 v  = ((const float4*)xx)[i];
    float4 wv = ((const float4*)w)[sm];
    float4 bv = ((const float4*)bbp)[sm];
    float4 o;
    o.x = (v.x - mean) * rstd * wv.x + bv.x;
    o.y = (v.y - mean) * rstd * wv.y + bv.y;
    o.z = (v.z - mean) * rstd * wv.z + bv.z;
    o.w = (v.w - mean) * rstd * wv.w + bv.w;
    ((float4*)y)[i] = o;
}

// ---------------------------------------------------------------------------
// Launch
// ---------------------------------------------------------------------------
extern "C" void kernel_launch(void* const* d_in, const int* in_sizes, int n_in,
                              void* d_out, int out_size)
{
    const float* x     = (const float*)d_in[0];
    const float* w_out = (const float*)d_in[1];
    const float* ln1_w = (const float*)d_in[2];
    const float* ln1_b = (const float*)d_in[3];
    const float* w1    = (const float*)d_in[4];
    const float* b1    = (const float*)d_in[5];
    const float* w2    = (const float*)d_in[6];
    const float* b2    = (const float*)d_in[7];
    const float* ln2_w = (const float*)d_in[8];
    const float* ln2_b = (const float*)d_in[9];
    float* out = (float*)d_out;

    float *scores, *ctx, *xt, *pre1, *h, *ff1, *pre2, *part, *stats;
    cudaGetSymbolAddress((void**)&scores, g_scores);
    cudaGetSymbolAddress((void**)&ctx,    g_ctx);
    cudaGetSymbolAddress((void**)&xt,     g_xt);
    cudaGetSymbolAddress((void**)&pre1,   g_pre1);
    cudaGetSymbolAddress((void**)&h,      g_h);
    cudaGetSymbolAddress((void**)&ff1,    g_ff1);
    cudaGetSymbolAddress((void**)&pre2,   g_pre2);
    cudaGetSymbolAddress((void**)&part,   g_part);
    cudaGetSymbolAddress((void**)&stats,  g_stats);

    cudaFuncSetAttribute(gemm_mma<0>, cudaFuncAttributeMaxDynamicSharedMemorySize, SMEM_TOT);
    cudaFuncSetAttribute(gemm_mma<1>, cudaFuncAttributeMaxDynamicSharedMemorySize, SMEM_TOT);
    cudaFuncSetAttribute(gemm_mma<2>, cudaFuncAttributeMaxDynamicSharedMemorySize, SMEM_TOT);
    cudaFuncSetAttribute(gemm_mma<3>, cudaFuncAttributeMaxDynamicSharedMemorySize, SMEM_TOT);
    cudaFuncSetAttribute(gemm_mma<4>, cudaFuncAttributeMaxDynamicSharedMemorySize, SMEM_TOT);

    dim3 blk(256);
    const float scale = 1.0f / 32.0f;   // 1/sqrt(1024)
    const long SSQ = (long)SS * SS;

    // 1. scores = (x @ x^T) * scale     per-batch NT: M=2048, N=2048, K=1024
    gemm_mma<0><<<dim3(SS / 128, SS / 128, BB), blk, SMEM_TOT>>>(
        x, x, scores, nullptr, nullptr, MM, SS, SMTOT, SMTOT, SSQ, scale);

    // 1b. xT (independent of scores)
    transpose_k<<<dim3(MM / 32, SS / 32, BB), dim3(32, 8)>>>(x, xt);

    // 2. softmax rows (in place)
    softmax_k<<<(unsigned)(BB * SS), blk>>>(scores);

    // 3. ctx = attn @ x                per-batch NT with B = xT: M=2048, N=1024, K=2048
    gemm_mma<1><<<dim3(MM / 128, SS / 128, BB), blk, SMEM_TOT>>>(
        scores, xt, ctx, nullptr, nullptr, SS, MM, SSQ, SMTOT, SMTOT, 1.f);

    // 4. pre1 = ctx @ w_out^T + x      folded: M=8192, N=1024, K=1024
    gemm_mma<2><<<dim3(MM / 128, (BB * SS) / 128, 1), blk, SMEM_TOT>>>(
        ctx, w_out, pre1, nullptr, x, MM, MM, 0, 0, 0, 1.f);

    // 5. h = LN1(pre1)
    ln_reduce_k<<<dim3(256, BB), blk>>>(pre1, part);
    ln_finalize_k<<<BB, blk>>>(part, stats);
    ln_apply_k<<<(unsigned)((BB * SMTOT / 4) / 256), blk>>>(pre1, ln1_w, ln1_b, stats, h);

    // 6. ff1 = relu(h @ w1^T + b1)     folded: M=8192, N=4096, K=1024
    gemm_mma<3><<<dim3(FF / 128, (BB * SS) / 128, 1), blk, SMEM_TOT>>>(
        h, w1, ff1, b1, nullptr, MM, FF, 0, 0, 0, 1.f);

    // 7. pre2 = ff1 @ w2^T + b2 + h    folded: M=8192, N=1024, K=4096
    gemm_mma<4><<<dim3(MM / 128, (BB * SS) / 128, 1), blk, SMEM_TOT>>>(
        ff1, w2, pre2, b2, h, FF, MM, 0, 0, 0, 1.f);

    // 8. out = LN2(pre2)
    ln_reduce_k<<<dim3(256, BB), blk>>>(pre2, part);
    ln_finalize_k<<<BB, blk>>>(part, stats);
    ln_apply_k<<<(unsigned)((BB * SMTOT / 4) / 256), blk>>>(pre2, ln2_w, ln2_b, stats, out);
}

// round 4
// speedup vs baseline: 3.1130x; 1.7189x over previous
#include <cuda_runtime.h>
#include <cuda_fp16.h>
#include <stdint.h>
#include <math.h>

// ---------------------------------------------------------------------------
// Problem constants
// ---------------------------------------------------------------------------
#define BB 4
#define SS 2048
#define MM 1024
#define FF 4096
static const long SMTOT = (long)SS * MM;
static const long SM4   = SMTOT / 4;

// ---------------------------------------------------------------------------
// Scratch (device globals)
// ---------------------------------------------------------------------------
__device__ float g_scores[(long)BB * SS * SS];   // 64 MB
__device__ float g_ctx   [(long)BB * SS * MM];
__device__ float g_xt    [(long)BB * SS * MM];
__device__ float g_pre1  [(long)BB * SS * MM];
__device__ float g_h     [(long)BB * SS * MM];
__device__ float g_ff1   [(long)BB * SS * FF];   // 128 MB
__device__ float g_pre2  [(long)BB * SS * MM];
__device__ float g_part  [BB * 256 * 2];
__device__ float g_stats [BB * 2];

// ---------------------------------------------------------------------------
// helpers
// ---------------------------------------------------------------------------
static __device__ __forceinline__ uint32_t smem_u32(const void* p) {
    uint32_t a;
    asm("{ .reg .u64 t; cvta.to.shared.u64 t, %1; cvt.u32.u64 %0, t; }"
        : "=r"(a) : "l"(p));
    return a;
}

static __device__ __forceinline__ uint32_t pack_h2(float lo, float hi) {
    __half2 h = __floats2half2_rn(lo, hi);
    return *reinterpret_cast<uint32_t*>(&h);
}

static __device__ __forceinline__ void ldsm4(uint32_t* r, uint32_t addr) {
    asm volatile("ldmatrix.sync.aligned.m8n8.x4.shared.b16 {%0,%1,%2,%3}, [%4];"
                 : "=r"(r[0]), "=r"(r[1]), "=r"(r[2]), "=r"(r[3]) : "r"(addr));
}

static __device__ __forceinline__ void mma_f16(
    float& c0, float& c1, float& c2, float& c3,
    uint32_t a0, uint32_t a1, uint32_t a2, uint32_t a3,
    uint32_t b0, uint32_t b1)
{
    asm volatile(
        "mma.sync.aligned.m16n8k16.row.col.f32.f16.f16.f32 "
        "{%0,%1,%2,%3}, {%4,%5,%6,%7}, {%8,%9}, {%0,%1,%2,%3};"
        : "+f"(c0), "+f"(c1), "+f"(c2), "+f"(c3)
        : "r"(a0), "r"(a1), "r"(a2), "r"(a3), "r"(b0), "r"(b1));
}

// ---------------------------------------------------------------------------
// fp16 NT GEMM via mma.sync + ldmatrix:  C[m,n] = epi( sum_k A[m,k]*B[n,k] )
// A: [M,K] f32 row-major, B: [N,K] f32 row-major; converted to f16 at staging.
// BM=BN=128, BK=32; 256 threads; warps 2(m) x 4(n); warp tile 64x32.
// Smem rows padded to 40 halfs (80 B): ldmatrix phases conflict-free.
// EPI: 0=*alpha  1=plain  2=+R  3=relu(+bias)  4=+bias+R
// ---------------------------------------------------------------------------
#define ROWH 40
#define TILE_H (128 * ROWH)                 // halfs per matrix per buffer
#define SMEM_TOT (4 * TILE_H * 2)           // bytes (A0,A1,B0,B1)

template<int EPI>
__global__ __launch_bounds__(256)
void gemm_h(const float* __restrict__ A, const float* __restrict__ Bm,
            float* __restrict__ C, const float* __restrict__ bias,
            const float* __restrict__ R,
            int Kdim, int Ndim, long sA, long sB, long sC, float alpha)
{
    extern __shared__ __align__(16) uint16_t sm16[];
    uint16_t* As[2] = { sm16,              sm16 + TILE_H };
    uint16_t* Bs[2] = { sm16 + 2 * TILE_H, sm16 + 3 * TILE_H };

    const int tid  = threadIdx.x;
    const int wid  = tid >> 5;
    const int lane = tid & 31;
    const int gid  = lane >> 2;        // 0..7
    const int lq   = lane & 3;         // 0..3
    const int wm   = wid >> 2;         // 0..1 (m)
    const int wn   = wid & 3;          // 0..3 (n)

    const long bz = blockIdx.z;
    const int  m0 = blockIdx.y * 128;
    const int  n0 = blockIdx.x * 128;

    // staging: each thread loads 16 A floats + 16 B floats per BK tile
    const int lrow = tid >> 1;          // 0..127
    const int kh   = (tid & 1) * 16;    // half-index 0 / 16

    const float* Ag = A  + bz * sA + (long)(m0 + lrow) * Kdim + kh;
    const float* Bg = Bm + bz * sB + (long)(n0 + lrow) * Kdim + kh;

    // ldmatrix lane addressing
    const int g8  = lane >> 3;          // 0..3
    const int r8  = lane & 7;           // 0..7
    const int ro8 = (g8 & 1) * 8;       // row offset within 16
    const int co8 = (g8 >> 1) * 8;      // col offset (halfs) within 16

    const uint32_t smb = smem_u32(sm16);
    const uint32_t aBase[2] = { smb,                    smb + TILE_H * 2 };
    const uint32_t bBase[2] = { smb + 2 * TILE_H * 2,   smb + 3 * TILE_H * 2 };

    uint32_t aoff[4], boff[2];
    #pragma unroll
    for (int mt = 0; mt < 4; mt++)
        aoff[mt] = ((wm * 64 + mt * 16 + ro8 + r8) * ROWH + co8) * 2;
    #pragma unroll
    for (int p = 0; p < 2; p++)
        boff[p] = ((wn * 32 + p * 16 + ro8 + r8) * ROWH + co8) * 2;

    float acc[4][4][4];
    #pragma unroll
    for (int i = 0; i < 4; i++)
        #pragma unroll
        for (int j = 0; j < 4; j++)
            #pragma unroll
            for (int q = 0; q < 4; q++) acc[i][j][q] = 0.f;

    const int KT = Kdim >> 5;

    float4 ra[4], rb[4];
    #pragma unroll
    for (int j = 0; j < 4; j++) {
        ra[j] = *(const float4*)(Ag + j * 4);
        rb[j] = *(const float4*)(Bg + j * 4);
    }

    for (int kt = 0; kt < KT; kt++) {
        const int s = kt & 1;
        // stage: f32 -> f16x2, STS.128 x2 per matrix
        {
            uint16_t* ap = As[s] + lrow * ROWH + kh;
            uint16_t* bp = Bs[s] + lrow * ROWH + kh;
            uint4 ua0, ua1, ub0, ub1;
            ua0.x = pack_h2(ra[0].x, ra[0].y); ua0.y = pack_h2(ra[0].z, ra[0].w);
            ua0.z = pack_h2(ra[1].x, ra[1].y); ua0.w = pack_h2(ra[1].z, ra[1].w);
            ua1.x = pack_h2(ra[2].x, ra[2].y); ua1.y = pack_h2(ra[2].z, ra[2].w);
            ua1.z = pack_h2(ra[3].x, ra[3].y); ua1.w = pack_h2(ra[3].z, ra[3].w);
            ub0.x = pack_h2(rb[0].x, rb[0].y); ub0.y = pack_h2(rb[0].z, rb[0].w);
            ub0.z = pack_h2(rb[1].x, rb[1].y); ub0.w = pack_h2(rb[1].z, rb[1].w);
            ub1.x = pack_h2(rb[2].x, rb[2].y); ub1.y = pack_h2(rb[2].z, rb[2].w);
            ub1.z = pack_h2(rb[3].x, rb[3].y); ub1.w = pack_h2(rb[3].z, rb[3].w);
            *(uint4*)(ap)     = ua0;
            *(uint4*)(ap + 8) = ua1;
            *(uint4*)(bp)     = ub0;
            *(uint4*)(bp + 8) = ub1;
        }
        __syncthreads();

        if (kt + 1 < KT) {
            const float* an = Ag + (kt + 1) * 32;
            const float* bn = Bg + (kt + 1) * 32;
            #pragma unroll
            for (int j = 0; j < 4; j++) {
                ra[j] = *(const float4*)(an + j * 4);
                rb[j] = *(const float4*)(bn + j * 4);
            }
        }

        // 2 k16-steps from buffer s
        #pragma unroll
        for (int ks = 0; ks < 2; ks++) {
            const uint32_t kb = ks * 32;   // 16 halfs * 2 bytes
            uint32_t af[4][4];
            #pragma unroll
            for (int mt = 0; mt < 4; mt++)
                ldsm4(af[mt], aBase[s] + aoff[mt] + kb);
            uint32_t bf[2][4];
            #pragma unroll
            for (int p = 0; p < 2; p++)
                ldsm4(bf[p], bBase[s] + boff[p] + kb);
            #pragma unroll
            for (int mt = 0; mt < 4; mt++)
                #pragma unroll
                for (int nt = 0; nt < 4; nt++) {
                    const int pr = nt >> 1, od = nt & 1;
                    mma_f16(acc[mt][nt][0], acc[mt][nt][1],
                            acc[mt][nt][2], acc[mt][nt][3],
                            af[mt][0], af[mt][1], af[mt][2], af[mt][3],
                            bf[pr][od], bf[pr][od + 2]);
                }
        }
        __syncthreads();
    }

    // ---------------- epilogue ----------------
    float* Cb = C + bz * sC;
    #pragma unroll
    for (int mt = 0; mt < 4; mt++) {
        const long row0 = m0 + wm * 64 + mt * 16 + gid;
        #pragma unroll
        for (int nt = 0; nt < 4; nt++) {
            const long col = n0 + wn * 32 + nt * 8 + lq * 2;
            float v0 = acc[mt][nt][0], v1 = acc[mt][nt][1];
            float v2 = acc[mt][nt][2], v3 = acc[mt][nt][3];
            if (EPI == 0) { v0 *= alpha; v1 *= alpha; v2 *= alpha; v3 *= alpha; }
            if (EPI == 3 || EPI == 4) {
                float2 b2 = *(const float2*)(bias + col);
                v0 += b2.x; v1 += b2.y; v2 += b2.x; v3 += b2.y;
            }
            if (EPI == 3) {
                v0 = fmaxf(v0, 0.f); v1 = fmaxf(v1, 0.f);
                v2 = fmaxf(v2, 0.f); v3 = fmaxf(v3, 0.f);
            }
            const long o0 = row0 * (long)Ndim + col;
            const long o1 = (row0 + 8) * (long)Ndim + col;
            if (EPI == 2 || EPI == 4) {
                float2 r0 = *(const float2*)(R + o0);
                float2 r1 = *(const float2*)(R + o1);
                v0 += r0.x; v1 += r0.y; v2 += r1.x; v3 += r1.y;
            }
            *(float2*)(Cb + o0) = make_float2(v0, v1);
            *(float2*)(Cb + o1) = make_float2(v2, v3);
        }
    }
}

// ---------------------------------------------------------------------------
// Transpose per batch: xt[b][m][s] = x[b][s][m]
// ---------------------------------------------------------------------------
__global__ __launch_bounds__(256)
void transpose_k(const float* __restrict__ x, float* __restrict__ xt)
{
    __shared__ float t[32][33];
    const int b  = blockIdx.z;
    const int bx = blockIdx.x * 32;
    const int by = blockIdx.y * 32;
    const float* xp = x  + (long)b * SMTOT;
    float*       yp = xt + (long)b * SMTOT;
    const int txx = threadIdx.x, tyy = threadIdx.y;
    #pragma unroll
    for (int i = 0; i < 4; i++)
        t[tyy + i * 8][txx] = xp[(long)(by + tyy + i * 8) * MM + bx + txx];
    __syncthreads();
    #pragma unroll
    for (int i = 0; i < 4; i++)
        yp[(long)(bx + tyy + i * 8) * SS + by + txx] = t[txx][tyy + i * 8];
}

// ---------------------------------------------------------------------------
// Row softmax over 2048 columns (in place)
// ---------------------------------------------------------------------------
__global__ __launch_bounds__(256)
void softmax_k(float* __restrict__ data)
{
    long row = blockIdx.x;
    float* p = data + row * (long)SS;
    int t = threadIdx.x;
    float v[8];
    float mx = -INFINITY;
    #pragma unroll
    for (int i = 0; i < 8; i++) { v[i] = p[t + i * 256]; mx = fmaxf(mx, v[i]); }
    __shared__ float red[256];
    red[t] = mx; __syncthreads();
    for (int s = 128; s > 0; s >>= 1) {
        if (t < s) red[t] = fmaxf(red[t], red[t + s]);
        __syncthreads();
    }
    mx = red[0];
    __syncthreads();
    float sum = 0.f;
    #pragma unroll
    for (int i = 0; i < 8; i++) { v[i] = __expf(v[i] - mx); sum += v[i]; }
    red[t] = sum; __syncthreads();
    for (int s = 128; s > 0; s >>= 1) {
        if (t < s) red[t] += red[t + s];
        __syncthreads();
    }
    float inv = 1.f / red[0];
    #pragma unroll
    for (int i = 0; i < 8; i++) p[t + i * 256] = v[i] * inv;
}

// ---------------------------------------------------------------------------
// LayerNorm over full (S,M) plane per batch — deterministic 3-stage
// ---------------------------------------------------------------------------
__global__ __launch_bounds__(256)
void ln_reduce_k(const float* __restrict__ xx, float* __restrict__ part)
{
    int b = blockIdx.y;
    const float4* p = (const float4*)(xx + (long)b * SMTOT) + (long)blockIdx.x * 2048;
    float s = 0.f, q = 0.f;
    for (int i = threadIdx.x; i < 2048; i += 256) {
        float4 v = p[i];
        s += v.x + v.y + v.z + v.w;
        q += v.x * v.x + v.y * v.y + v.z * v.z + v.w * v.w;
    }
    __shared__ float rs[256], rq[256];
    rs[threadIdx.x] = s; rq[threadIdx.x] = q; __syncthreads();
    for (int st = 128; st > 0; st >>= 1) {
        if (threadIdx.x < st) {
            rs[threadIdx.x] += rs[threadIdx.x + st];
            rq[threadIdx.x] += rq[threadIdx.x + st];
        }
        __syncthreads();
    }
    if (threadIdx.x == 0) {
        int idx = (b * 256 + blockIdx.x) * 2;
        part[idx]     = rs[0];
        part[idx + 1] = rq[0];
    }
}

__global__ __launch_bounds__(256)
void ln_finalize_k(const float* __restrict__ part, float* __restrict__ stats)
{
    int b = blockIdx.x, t = threadIdx.x;
    float s = part[(b * 256 + t) * 2];
    float q = part[(b * 256 + t) * 2 + 1];
    __shared__ float rs[256], rq[256];
    rs[t] = s; rq[t] = q; __syncthreads();
    for (int st = 128; st > 0; st >>= 1) {
        if (t < st) { rs[t] += rs[t + st]; rq[t] += rq[t + st]; }
        __syncthreads();
    }
    if (t == 0) {
        float mean = rs[0] / (float)SMTOT;
        float var  = rq[0] / (float)SMTOT - mean * mean;
        stats[b * 2]     = mean;
        stats[b * 2 + 1] = rsqrtf(var + 1e-5f);
    }
}

__global__ __launch_bounds__(256)
void ln_apply_k(const float* __restrict__ xx, const float* __restrict__ w,
                const float* __restrict__ bbp, const float* __restrict__ stats,
                float* __restrict__ y)
{
    long i = (long)blockIdx.x * 256 + threadIdx.x;
    int b  = (int)(i / SM4);
    long sm = i - (long)b * SM4;
    float mean = stats[b * 2];
    float rstd = stats[b * 2 + 1];
    float4 v  = ((const float4*)xx)[i];
    float4 wv = ((const float4*)w)[sm];
    float4 bv = ((const float4*)bbp)[sm];
    float4 o;
    o.x = (v.x - mean) * rstd * wv.x + bv.x;
    o.y = (v.y - mean) * rstd * wv.y + bv.y;
    o.z = (v.z - mean) * rstd * wv.z + bv.z;
    o.w = (v.w - mean) * rstd * wv.w + bv.w;
    ((float4*)y)[i] = o;
}

// ---------------------------------------------------------------------------
// Launch
// ---------------------------------------------------------------------------
extern "C" void kernel_launch(void* const* d_in, const int* in_sizes, int n_in,
                              void* d_out, int out_size)
{
    const float* x     = (const float*)d_in[0];
    const float* w_out = (const float*)d_in[1];
    const float* ln1_w = (const float*)d_in[2];
    const float* ln1_b = (const float*)d_in[3];
    const float* w1    = (const float*)d_in[4];
    const float* b1    = (const float*)d_in[5];
    const float* w2    = (const float*)d_in[6];
    const float* b2    = (const float*)d_in[7];
    const float* ln2_w = (const float*)d_in[8];
    const float* ln2_b = (const float*)d_in[9];
    float* out = (float*)d_out;

    float *scores, *ctx, *xt, *pre1, *h, *ff1, *pre2, *part, *stats;
    cudaGetSymbolAddress((void**)&scores, g_scores);
    cudaGetSymbolAddress((void**)&ctx,    g_ctx);
    cudaGetSymbolAddress((void**)&xt,     g_xt);
    cudaGetSymbolAddress((void**)&pre1,   g_pre1);
    cudaGetSymbolAddress((void**)&h,      g_h);
    cudaGetSymbolAddress((void**)&ff1,    g_ff1);
    cudaGetSymbolAddress((void**)&pre2,   g_pre2);
    cudaGetSymbolAddress((void**)&part,   g_part);
    cudaGetSymbolAddress((void**)&stats,  g_stats);

    cudaFuncSetAttribute(gemm_h<0>, cudaFuncAttributeMaxDynamicSharedMemorySize, SMEM_TOT);
    cudaFuncSetAttribute(gemm_h<1>, cudaFuncAttributeMaxDynamicSharedMemorySize, SMEM_TOT);
    cudaFuncSetAttribute(gemm_h<2>, cudaFuncAttributeMaxDynamicSharedMemorySize, SMEM_TOT);
    cudaFuncSetAttribute(gemm_h<3>, cudaFuncAttributeMaxDynamicSharedMemorySize, SMEM_TOT);
    cudaFuncSetAttribute(gemm_h<4>, cudaFuncAttributeMaxDynamicSharedMemorySize, SMEM_TOT);

    dim3 blk(256);
    const float scale = 1.0f / 32.0f;   // 1/sqrt(1024)
    const long SSQ = (long)SS * SS;

    // 1. scores = (x @ x^T) * scale     per-batch NT: M=2048, N=2048, K=1024
    gemm_h<0><<<dim3(SS / 128, SS / 128, BB), blk, SMEM_TOT>>>(
        x, x, scores, nullptr, nullptr, MM, SS, SMTOT, SMTOT, SSQ, scale);

    // 1b. xT (independent of scores)
    transpose_k<<<dim3(MM / 32, SS / 32, BB), dim3(32, 8)>>>(x, xt);

    // 2. softmax rows (in place)
    softmax_k<<<(unsigned)(BB * SS), blk>>>(scores);

    // 3. ctx = attn @ x                per-batch NT with B = xT: M=2048, N=1024, K=2048
    gemm_h<1><<<dim3(MM / 128, SS / 128, BB), blk, SMEM_TOT>>>(
        scores, xt, ctx, nullptr, nullptr, SS, MM, SSQ, SMTOT, SMTOT, 1.f);

    // 4. pre1 = ctx @ w_out^T + x      folded: M=8192, N=1024, K=1024
    gemm_h<2><<<dim3(MM / 128, (BB * SS) / 128, 1), blk, SMEM_TOT>>>(
        ctx, w_out, pre1, nullptr, x, MM, MM, 0, 0, 0, 1.f);

    // 5. h = LN1(pre1)
    ln_reduce_k<<<dim3(256, BB), blk>>>(pre1, part);
    ln_finalize_k<<<BB, blk>>>(part, stats);
    ln_apply_k<<<(unsigned)((BB * SMTOT / 4) / 256), blk>>>(pre1, ln1_w, ln1_b, stats, h);

    // 6. ff1 = relu(h @ w1^T + b1)     folded: M=8192, N=4096, K=1024
    gemm_h<3><<<dim3(FF / 128, (BB * SS) / 128, 1), blk, SMEM_TOT>>>(
        h, w1, ff1, b1, nullptr, MM, FF, 0, 0, 0, 1.f);

    // 7. pre2 = ff1 @ w2^T + b2 + h    folded: M=8192, N=1024, K=4096
    gemm_h<4><<<dim3(MM / 128, (BB * SS) / 128, 1), blk, SMEM_TOT>>>(
        ff1, w2, pre2, b2, h, FF, MM, 0, 0, 0, 1.f);

    // 8. out = LN2(pre2)
    ln_reduce_k<<<dim3(256, BB), blk>>>(pre2, part);
    ln_finalize_k<<<BB, blk>>>(part, stats);
    ln_apply_k<<<(unsigned)((BB * SMTOT / 4) / 256), blk>>>(pre2, ln2_w, ln2_b, stats, out);
}

// round 5
// speedup vs baseline: 5.5303x; 1.7765x over previous
#include <cuda_runtime.h>
#include <cuda_fp16.h>
#include <stdint.h>
#include <math.h>

// ---------------------------------------------------------------------------
// Problem constants
// ---------------------------------------------------------------------------
#define BB 4
#define SS 2048
#define MM 1024
#define FF 4096
static const long SMTOT = (long)SS * MM;
static const long SM4   = SMTOT / 4;

// ---------------------------------------------------------------------------
// Scratch (device globals)
// ---------------------------------------------------------------------------
__device__ float  g_scores[(long)BB * SS * SS];   // 64 MB
__device__ float  g_pre1  [(long)BB * SS * MM];
__device__ float  g_h     [(long)BB * SS * MM];
__device__ float  g_pre2  [(long)BB * SS * MM];
__device__ float  g_part  [BB * 256 * 2];
__device__ float  g_stats [BB * 2];

__device__ __half g_x16   [(long)BB * SS * MM];   // 16 MB
__device__ __half g_xt16  [(long)BB * SS * MM];   // 16 MB  [B,M,S]
__device__ __half g_attn16[(long)BB * SS * SS];   // 32 MB
__device__ __half g_ctx16 [(long)BB * SS * MM];   // 16 MB
__device__ __half g_h16   [(long)BB * SS * MM];   // 16 MB
__device__ __half g_ff116 [(long)BB * SS * FF];   // 64 MB
__device__ __half g_wout16[(long)MM * MM];
__device__ __half g_w116  [(long)FF * MM];
__device__ __half g_w216  [(long)MM * FF];

// ---------------------------------------------------------------------------
// helpers
// ---------------------------------------------------------------------------
static __device__ __forceinline__ uint32_t smem_u32(const void* p) {
    uint32_t a;
    asm("{ .reg .u64 t; cvta.to.shared.u64 t, %1; cvt.u32.u64 %0, t; }"
        : "=r"(a) : "l"(p));
    return a;
}

static __device__ __forceinline__ void cp16(uint32_t saddr, const void* gaddr) {
    asm volatile("cp.async.cg.shared.global [%0], [%1], 16;"
                 :: "r"(saddr), "l"(gaddr) : "memory");
}
static __device__ __forceinline__ void cp_commit() {
    asm volatile("cp.async.commit_group;" ::: "memory");
}
template<int N>
static __device__ __forceinline__ void cp_wait() {
    asm volatile("cp.async.wait_group %0;" :: "n"(N) : "memory");
}

static __device__ __forceinline__ void ldsm4(uint32_t* r, uint32_t addr) {
    asm volatile("ldmatrix.sync.aligned.m8n8.x4.shared.b16 {%0,%1,%2,%3}, [%4];"
                 : "=r"(r[0]), "=r"(r[1]), "=r"(r[2]), "=r"(r[3]) : "r"(addr));
}

static __device__ __forceinline__ void mma_f16(
    float& c0, float& c1, float& c2, float& c3,
    uint32_t a0, uint32_t a1, uint32_t a2, uint32_t a3,
    uint32_t b0, uint32_t b1)
{
    asm volatile(
        "mma.sync.aligned.m16n8k16.row.col.f32.f16.f16.f32 "
        "{%0,%1,%2,%3}, {%4,%5,%6,%7}, {%8,%9}, {%0,%1,%2,%3};"
        : "+f"(c0), "+f"(c1), "+f"(c2), "+f"(c3)
        : "r"(a0), "r"(a1), "r"(a2), "r"(a3), "r"(b0), "r"(b1));
}

// ---------------------------------------------------------------------------
// fp16 NT GEMM, cp.async 3-stage pipeline:
//   C[m,n] = epi( sum_k A[m,k]*B[n,k] ),  A:[M,K] f16, B:[N,K] f16 row-major.
// BM=BN=128, BK=64; 256 threads; warps 2(m) x 4(n); warp tile 64x32.
// Smem rows = 128 B (64 halfs), SW128 swizzle (16B unit ^= row&7).
// EPI: 0=*alpha(->f32)  1=plain(->f16)  2=+R(->f32)  3=relu+bias(->f16)
//      4=+bias+R(->f32)
// ---------------------------------------------------------------------------
#define STAGES     3
#define STAGE_B    32768          // 2 matrices * 128 rows * 128 B
#define SMEM_TOT   (STAGES * STAGE_B)

template<int EPI, typename OT>
__global__ __launch_bounds__(256, 2)
void gemm_h16(const __half* __restrict__ A, const __half* __restrict__ Bm,
              OT* __restrict__ C, const float* __restrict__ bias,
              const float* __restrict__ R,
              int Kdim, int Ndim, long sA, long sB, long sC, float alpha)
{
    extern __shared__ __align__(1024) char sm[];
    const uint32_t smb = smem_u32(sm);

    const int tid  = threadIdx.x;
    const int wid  = tid >> 5;
    const int lane = tid & 31;
    const int gid  = lane >> 2;
    const int lq   = lane & 3;
    const int wm   = wid >> 2;      // 0..1
    const int wn   = wid & 3;       // 0..3

    const long bz = blockIdx.z;
    const int  m0 = blockIdx.y * 128;
    const int  n0 = blockIdx.x * 128;

    // ---- cp.async loader mapping: thread -> (row, 4 consecutive 16B units)
    const int lr = tid >> 1;            // 0..127
    const int lu = (tid & 1) * 4;       // 0 or 4
    const int lswz = lr & 7;
    const char* Agb = (const char*)(A  + bz * sA + (long)(m0 + lr) * Kdim);
    const char* Bgb = (const char*)(Bm + bz * sB + (long)(n0 + lr) * Kdim);
    const uint32_t sArow = lr * 128;

    // ---- ldmatrix addressing
    const int g8  = lane >> 3;
    const int r8  = lane & 7;
    const int ro8 = (g8 & 1) * 8;
    const int cbit = g8 >> 1;           // 0/1 : 16B unit within k16

    uint32_t aRowOff[4]; int aSwz[4];
    #pragma unroll
    for (int mt = 0; mt < 4; mt++) {
        int r = wm * 64 + mt * 16 + ro8 + r8;
        aRowOff[mt] = r * 128;
        aSwz[mt] = r & 7;
    }
    uint32_t bRowOff[2]; int bSwz[2];
    #pragma unroll
    for (int p = 0; p < 2; p++) {
        int r = wn * 32 + p * 16 + ro8 + r8;
        bRowOff[p] = r * 128;
        bSwz[p] = r & 7;
    }

    float acc[4][4][4];
    #pragma unroll
    for (int i = 0; i < 4; i++)
        #pragma unroll
        for (int j = 0; j < 4; j++)
            #pragma unroll
            for (int q = 0; q < 4; q++) acc[i][j][q] = 0.f;

    const int KT = Kdim >> 6;   // BK=64

    // stage loader
    auto load_stage = [&](int s, int kt) {
        const uint32_t sa = smb + s * STAGE_B + sArow;
        const uint32_t sb = sa + 16384;
        const long gk = (long)kt * 128;   // bytes along K
        #pragma unroll
        for (int i = 0; i < 4; i++) {
            const int u = lu + i;
            const uint32_t so = ((u ^ lswz) << 4);
            cp16(sa + so, Agb + gk + u * 16);
            cp16(sb + so, Bgb + gk + u * 16);
        }
    };

    load_stage(0, 0); cp_commit();
    if (KT > 1) load_stage(1, 1);
    cp_commit();

    for (int kt = 0; kt < KT; kt++) {
        const int s = kt % 3;
        cp_wait<1>();
        __syncthreads();
        if (kt + 2 < KT) load_stage((kt + 2) % 3, kt + 2);
        cp_commit();

        const uint32_t aBase = smb + s * STAGE_B;
        const uint32_t bBase = aBase + 16384;
        #pragma unroll
        for (int ks = 0; ks < 4; ks++) {
            const int u = ks * 2 + cbit;
            uint32_t af[4][4];
            #pragma unroll
            for (int mt = 0; mt < 4; mt++)
                ldsm4(af[mt], aBase + aRowOff[mt] + ((u ^ aSwz[mt]) << 4));
            uint32_t bf[2][4];
            #pragma unroll
            for (int p = 0; p < 2; p++)
                ldsm4(bf[p], bBase + bRowOff[p] + ((u ^ bSwz[p]) << 4));
            #pragma unroll
            for (int mt = 0; mt < 4; mt++)
                #pragma unroll
                for (int nt = 0; nt < 4; nt++) {
                    const int pr = nt >> 1, od = nt & 1;
                    mma_f16(acc[mt][nt][0], acc[mt][nt][1],
                            acc[mt][nt][2], acc[mt][nt][3],
                            af[mt][0], af[mt][1], af[mt][2], af[mt][3],
                            bf[pr][od], bf[pr][od + 2]);
                }
        }
        __syncthreads();
    }

    // ---------------- epilogue ----------------
    OT* Cb = C + bz * sC;
    #pragma unroll
    for (int mt = 0; mt < 4; mt++) {
        const long row0 = m0 + wm * 64 + mt * 16 + gid;
        #pragma unroll
        for (int nt = 0; nt < 4; nt++) {
            const long col = n0 + wn * 32 + nt * 8 + lq * 2;
            float v0 = acc[mt][nt][0], v1 = acc[mt][nt][1];
            float v2 = acc[mt][nt][2], v3 = acc[mt][nt][3];
            if (EPI == 0) { v0 *= alpha; v1 *= alpha; v2 *= alpha; v3 *= alpha; }
            if (EPI == 3 || EPI == 4) {
                float2 b2 = *(const float2*)(bias + col);
                v0 += b2.x; v1 += b2.y; v2 += b2.x; v3 += b2.y;
            }
            if (EPI == 3) {
                v0 = fmaxf(v0, 0.f); v1 = fmaxf(v1, 0.f);
                v2 = fmaxf(v2, 0.f); v3 = fmaxf(v3, 0.f);
            }
            const long o0 = row0 * (long)Ndim + col;
            const long o1 = (row0 + 8) * (long)Ndim + col;
            if (EPI == 2 || EPI == 4) {
                float2 r0 = *(const float2*)(R + o0);
                float2 r1 = *(const float2*)(R + o1);
                v0 += r0.x; v1 += r0.y; v2 += r1.x; v3 += r1.y;
            }
            if (sizeof(OT) == 4) {
                *(float2*)((float*)Cb + o0) = make_float2(v0, v1);
                *(float2*)((float*)Cb + o1) = make_float2(v2, v3);
            } else {
                *(__half2*)((__half*)Cb + o0) = __floats2half2_rn(v0, v1);
                *(__half2*)((__half*)Cb + o1) = __floats2half2_rn(v2, v3);
            }
        }
    }
}

// ---------------------------------------------------------------------------
// f32 -> f16 elementwise convert
// ---------------------------------------------------------------------------
__global__ __launch_bounds__(256)
void cvt16_k(const float* __restrict__ in, __half* __restrict__ out, long n4)
{
    long i = (long)blockIdx.x * 256 + threadIdx.x;
    if (i >= n4) return;
    float4 v = ((const float4*)in)[i];
    __half2 a = __floats2half2_rn(v.x, v.y);
    __half2 b = __floats2half2_rn(v.z, v.w);
    ((__half2*)out)[i * 2]     = a;
    ((__half2*)out)[i * 2 + 1] = b;
}

// ---------------------------------------------------------------------------
// Transpose per batch to fp16: xt16[b][m][s] = x[b][s][m]
// ---------------------------------------------------------------------------
__global__ __launch_bounds__(256)
void transpose16_k(const float* __restrict__ x, __half* __restrict__ xt)
{
    __shared__ float t[32][33];
    const int b  = blockIdx.z;
    const int bx = blockIdx.x * 32;
    const int by = blockIdx.y * 32;
    const float* xp = x  + (long)b * SMTOT;
    __half*      yp = xt + (long)b * SMTOT;
    const int txx = threadIdx.x, tyy = threadIdx.y;
    #pragma unroll
    for (int i = 0; i < 4; i++)
        t[tyy + i * 8][txx] = xp[(long)(by + tyy + i * 8) * MM + bx + txx];
    __syncthreads();
    #pragma unroll
    for (int i = 0; i < 4; i++)
        yp[(long)(bx + tyy + i * 8) * SS + by + txx] = __float2half(t[txx][tyy + i * 8]);
}

// ---------------------------------------------------------------------------
// Row softmax over 2048 columns: read f32 scores, write f16 attn
// ---------------------------------------------------------------------------
__global__ __launch_bounds__(256)
void softmax_k(const float* __restrict__ scores, __half* __restrict__ attn)
{
    long row = blockIdx.x;
    const float* p = scores + row * (long)SS;
    __half* q = attn + row * (long)SS;
    int t = threadIdx.x;
    float v[8];
    float mx = -INFINITY;
    #pragma unroll
    for (int i = 0; i < 8; i++) { v[i] = p[t + i * 256]; mx = fmaxf(mx, v[i]); }
    __shared__ float red[256];
    red[t] = mx; __syncthreads();
    for (int s = 128; s > 0; s >>= 1) {
        if (t < s) red[t] = fmaxf(red[t], red[t + s]);
        __syncthreads();
    }
    mx = red[0];
    __syncthreads();
    float sum = 0.f;
    #pragma unroll
    for (int i = 0; i < 8; i++) { v[i] = __expf(v[i] - mx); sum += v[i]; }
    red[t] = sum; __syncthreads();
    for (int s = 128; s > 0; s >>= 1) {
        if (t < s) red[t] += red[t + s];
        __syncthreads();
    }
    float inv = 1.f / red[0];
    #pragma unroll
    for (int i = 0; i < 8; i++) q[t + i * 256] = __float2half(v[i] * inv);
}

// ---------------------------------------------------------------------------
// LayerNorm over full (S,M) plane per batch — deterministic 3-stage
// ---------------------------------------------------------------------------
__global__ __launch_bounds__(256)
void ln_reduce_k(const float* __restrict__ xx, float* __restrict__ part)
{
    int b = blockIdx.y;
    const float4* p = (const float4*)(xx + (long)b * SMTOT) + (long)blockIdx.x * 2048;
    float s = 0.f, q = 0.f;
    for (int i = threadIdx.x; i < 2048; i += 256) {
        float4 v = p[i];
        s += v.x + v.y + v.z + v.w;
        q += v.x * v.x + v.y * v.y + v.z * v.z + v.w * v.w;
    }
    __shared__ float rs[256], rq[256];
    rs[threadIdx.x] = s; rq[threadIdx.x] = q; __syncthreads();
    for (int st = 128; st > 0; st >>= 1) {
        if (threadIdx.x < st) {
            rs[threadIdx.x] += rs[threadIdx.x + st];
            rq[threadIdx.x] += rq[threadIdx.x + st];
        }
        __syncthreads();
    }
    if (threadIdx.x == 0) {
        int idx = (b * 256 + blockIdx.x) * 2;
        part[idx]     = rs[0];
        part[idx + 1] = rq[0];
    }
}

__global__ __launch_bounds__(256)
void ln_finalize_k(const float* __restrict__ part, float* __restrict__ stats)
{
    int b = blockIdx.x, t = threadIdx.x;
    float s = part[(b * 256 + t) * 2];
    float q = part[(b * 256 + t) * 2 + 1];
    __shared__ float rs[256], rq[256];
    rs[t] = s; rq[t] = q; __syncthreads();
    for (int st = 128; st > 0; st >>= 1) {
        if (t < st) { rs[t] += rs[t + st]; rq[t] += rq[t + st]; }
        __syncthreads();
    }
    if (t == 0) {
        float mean = rs[0] / (float)SMTOT;
        float var  = rq[0] / (float)SMTOT - mean * mean;
        stats[b * 2]     = mean;
        stats[b * 2 + 1] = rsqrtf(var + 1e-5f);
    }
}

// WH: also write fp16 copy
template<bool WH>
__global__ __launch_bounds__(256)
void ln_apply_k(const float* __restrict__ xx, const float* __restrict__ w,
                const float* __restrict__ bbp, const float* __restrict__ stats,
                float* __restrict__ y, __half* __restrict__ y16)
{
    long i = (long)blockIdx.x * 256 + threadIdx.x;
    int b  = (int)(i / SM4);
    long sm = i - (long)b * SM4;
    float mean = stats[b * 2];
    float rstd = stats[b * 2 + 1];
    float4 v  = ((const float4*)xx)[i];
    float4 wv = ((const float4*)w)[sm];
    float4 bv = ((const float4*)bbp)[sm];
    float4 o;
    o.x = (v.x - mean) * rstd * wv.x + bv.x;
    o.y = (v.y - mean) * rstd * wv.y + bv.y;
    o.z = (v.z - mean) * rstd * wv.z + bv.z;
    o.w = (v.w - mean) * rstd * wv.w + bv.w;
    ((float4*)y)[i] = o;
    if (WH) {
        ((__half2*)y16)[i * 2]     = __floats2half2_rn(o.x, o.y);
        ((__half2*)y16)[i * 2 + 1] = __floats2half2_rn(o.z, o.w);
    }
}

// ---------------------------------------------------------------------------
// Launch
// ---------------------------------------------------------------------------
extern "C" void kernel_launch(void* const* d_in, const int* in_sizes, int n_in,
                              void* d_out, int out_size)
{
    const float* x     = (const float*)d_in[0];
    const float* w_out = (const float*)d_in[1];
    const float* ln1_w = (const float*)d_in[2];
    const float* ln1_b = (const float*)d_in[3];
    const float* w1    = (const float*)d_in[4];
    const float* b1    = (const float*)d_in[5];
    const float* w2    = (const float*)d_in[6];
    const float* b2    = (const float*)d_in[7];
    const float* ln2_w = (const float*)d_in[8];
    const float* ln2_b = (const float*)d_in[9];
    float* out = (float*)d_out;

    float  *scores, *pre1, *h, *pre2, *part, *stats;
    __half *x16, *xt16, *attn16, *ctx16, *h16, *ff116, *wout16, *w116, *w216;
    cudaGetSymbolAddress((void**)&scores, g_scores);
    cudaGetSymbolAddress((void**)&pre1,   g_pre1);
    cudaGetSymbolAddress((void**)&h,      g_h);
    cudaGetSymbolAddress((void**)&pre2,   g_pre2);
    cudaGetSymbolAddress((void**)&part,   g_part);
    cudaGetSymbolAddress((void**)&stats,  g_stats);
    cudaGetSymbolAddress((void**)&x16,    g_x16);
    cudaGetSymbolAddress((void**)&xt16,   g_xt16);
    cudaGetSymbolAddress((void**)&attn16, g_attn16);
    cudaGetSymbolAddress((void**)&ctx16,  g_ctx16);
    cudaGetSymbolAddress((void**)&h16,    g_h16);
    cudaGetSymbolAddress((void**)&ff116,  g_ff116);
    cudaGetSymbolAddress((void**)&wout16, g_wout16);
    cudaGetSymbolAddress((void**)&w116,   g_w116);
    cudaGetSymbolAddress((void**)&w216,   g_w216);

    cudaFuncSetAttribute(gemm_h16<0, float>,  cudaFuncAttributeMaxDynamicSharedMemorySize, SMEM_TOT);
    cudaFuncSetAttribute(gemm_h16<1, __half>, cudaFuncAttributeMaxDynamicSharedMemorySize, SMEM_TOT);
    cudaFuncSetAttribute(gemm_h16<2, float>,  cudaFuncAttributeMaxDynamicSharedMemorySize, SMEM_TOT);
    cudaFuncSetAttribute(gemm_h16<3, __half>, cudaFuncAttributeMaxDynamicSharedMemorySize, SMEM_TOT);
    cudaFuncSetAttribute(gemm_h16<4, float>,  cudaFuncAttributeMaxDynamicSharedMemorySize, SMEM_TOT);

    dim3 blk(256);
    const float scale = 1.0f / 32.0f;   // 1/sqrt(1024)
    const long SSQ = (long)SS * SS;

    // 0. conversions (independent)
    cvt16_k<<<(unsigned)((BB * SMTOT / 4) / 256), blk>>>(x, x16, BB * SMTOT / 4);
    transpose16_k<<<dim3(MM / 32, SS / 32, BB), dim3(32, 8)>>>(x, xt16);
    cvt16_k<<<(unsigned)(((long)MM * MM / 4) / 256), blk>>>(w_out, wout16, (long)MM * MM / 4);
    cvt16_k<<<(unsigned)(((long)FF * MM / 4) / 256), blk>>>(w1, w116, (long)FF * MM / 4);
    cvt16_k<<<(unsigned)(((long)MM * FF / 4) / 256), blk>>>(w2, w216, (long)MM * FF / 4);

    // 1. scores = (x @ x^T) * scale     per-batch NT: M=2048, N=2048, K=1024
    gemm_h16<0, float><<<dim3(SS / 128, SS / 128, BB), blk, SMEM_TOT>>>(
        x16, x16, scores, nullptr, nullptr, MM, SS, SMTOT, SMTOT, SSQ, scale);

    // 2. softmax rows -> fp16
    softmax_k<<<(unsigned)(BB * SS), blk>>>(scores, attn16);

    // 3. ctx16 = attn @ x               per-batch NT with B = xt16
    gemm_h16<1, __half><<<dim3(MM / 128, SS / 128, BB), blk, SMEM_TOT>>>(
        attn16, xt16, ctx16, nullptr, nullptr, SS, MM, SSQ, SMTOT, SMTOT, 1.f);

    // 4. pre1 = ctx @ w_out^T + x       folded: M=8192, N=1024, K=1024
    gemm_h16<2, float><<<dim3(MM / 128, (BB * SS) / 128, 1), blk, SMEM_TOT>>>(
        ctx16, wout16, pre1, nullptr, x, MM, MM, 0, 0, 0, 1.f);

    // 5. h = LN1(pre1), h16
    ln_reduce_k<<<dim3(256, BB), blk>>>(pre1, part);
    ln_finalize_k<<<BB, blk>>>(part, stats);
    ln_apply_k<true><<<(unsigned)((BB * SMTOT / 4) / 256), blk>>>(pre1, ln1_w, ln1_b, stats, h, h16);

    // 6. ff116 = relu(h @ w1^T + b1)    folded: M=8192, N=4096, K=1024
    gemm_h16<3, __half><<<dim3(FF / 128, (BB * SS) / 128, 1), blk, SMEM_TOT>>>(
        h16, w116, ff116, b1, nullptr, MM, FF, 0, 0, 0, 1.f);

    // 7. pre2 = ff1 @ w2^T + b2 + h     folded: M=8192, N=1024, K=4096
    gemm_h16<4, float><<<dim3(MM / 128, (BB * SS) / 128, 1), blk, SMEM_TOT>>>(
        ff116, w216, pre2, b2, h, FF, MM, 0, 0, 0, 1.f);

    // 8. out = LN2(pre2)
    ln_reduce_k<<<dim3(256, BB), blk>>>(pre2, part);
    ln_finalize_k<<<BB, blk>>>(part, stats);
    ln_apply_k<false><<<(unsigned)((BB * SMTOT / 4) / 256), blk>>>(pre2, ln2_w, ln2_b, stats, out, nullptr);
}